// round 16
// baseline (speedup 1.0000x reference)
#include <cuda_runtime.h>
#include <cuda_bf16.h>
#include <math.h>

// ---------------- problem constants ----------------
#define BB 4
#define SS 512
#define DD 768
#define FF_ 3072
#define VV 30000
#define VPAD 30080
#define HH 12
#define MM 64
#define DH 64
#define NLAYERS 12

// ---------------- static device scratch ----------------
__device__ float g_x  [BB*SS*DD];
__device__ float g_y  [BB*SS*DD];
__device__ float g_bqkv[3*DD];
__device__ __nv_bfloat16 g_xb  [BB*SS*DD];
__device__ __nv_bfloat16 g_lnb [BB*SS*DD];
__device__ __nv_bfloat16 g_ob  [BB*SS*DD];
__device__ __nv_bfloat16 g_qb  [BB*HH*SS*DH];
__device__ __nv_bfloat16 g_kb  [BB*HH*SS*DH];
__device__ __nv_bfloat16 g_vb  [BB*HH*SS*DH];
__device__ __nv_bfloat16 g_h1b [BB*SS*FF_];
__device__ __nv_bfloat16 g_gb  [BB*MM*DD];
__device__ __nv_bfloat16 g_wqkv[3*DD*DD];   // [n=2304][k=768]
__device__ __nv_bfloat16 g_wow [DD*DD];     // [n][k]
__device__ __nv_bfloat16 g_w1w [FF_*DD];    // [3072][768]
__device__ __nv_bfloat16 g_w2w [DD*FF_];    // [768][3072]
__device__ __nv_bfloat16 g_wew [VPAD*DD];   // [30080][768], rows >= 30000 zero
__device__ int g_tok[BB*SS];

// ====================== PTX helpers (arch-portable) ====================
__device__ __forceinline__ unsigned smem_u32(const void* p) {
    unsigned a;
    asm("{ .reg .u64 t; cvta.to.shared.u64 t, %1; cvt.u32.u64 %0, t; }" : "=r"(a) : "l"(p));
    return a;
}
#define SWZ(off) ((unsigned)(off) ^ (((unsigned)(off) >> 3) & 0x70u))

#define CP_ASYNC16(dst, src) \
    asm volatile("cp.async.cg.shared.global [%0], [%1], 16;" :: "r"(dst), "l"(src))
#define CP_COMMIT() asm volatile("cp.async.commit_group;" ::: "memory")
#define CP_WAIT1()  asm volatile("cp.async.wait_group 1;" ::: "memory")
#define CP_WAIT0()  asm volatile("cp.async.wait_group 0;" ::: "memory")

#define LDSM4(r, addr) \
    asm volatile("ldmatrix.sync.aligned.m8n8.x4.shared.b16 {%0,%1,%2,%3}, [%4];" \
        : "=r"((r)[0]), "=r"((r)[1]), "=r"((r)[2]), "=r"((r)[3]) : "r"(addr))

#define LDSM4T(r, addr) \
    asm volatile("ldmatrix.sync.aligned.m8n8.x4.trans.shared.b16 {%0,%1,%2,%3}, [%4];" \
        : "=r"((r)[0]), "=r"((r)[1]), "=r"((r)[2]), "=r"((r)[3]) : "r"(addr))

#define MMA16816(c, a, b0, b1) \
    asm volatile("mma.sync.aligned.m16n8k16.row.col.f32.bf16.bf16.f32 " \
        "{%0,%1,%2,%3}, {%4,%5,%6,%7}, {%8,%9}, {%0,%1,%2,%3};" \
        : "+f"((c)[0]), "+f"((c)[1]), "+f"((c)[2]), "+f"((c)[3]) \
        : "r"((a)[0]), "r"((a)[1]), "r"((a)[2]), "r"((a)[3]), "r"(b0), "r"(b1))

__device__ __forceinline__ unsigned pack_bf16x2(float lo, float hi) {
    __nv_bfloat162 h = __float22bfloat162_rn(make_float2(lo, hi));
    return *(unsigned*)&h;
}

// ---------------- epilogue modes ----------------
#define EP_QKV   0
#define EP_OPROJ 1
#define EP_FFN1  2
#define EP_FFN2  3
#define EP_HEAD  4

// paired store: columns (c, c+1), c even, same row r
template<int EPI>
__device__ __forceinline__ void epi_store2(int r, int c, float v0, float v1,
                                           const float* __restrict__ bias,
                                           float* __restrict__ outp)
{
    if (EPI == EP_QKV) {
        int b = r >> 9, s = r & 511;
        float a0 = v0 + bias[c], a1 = v1 + bias[c + 1];
        int which = c / DD, rr = c - which * DD, h = rr >> 6, d = rr & 63;
        __nv_bfloat16* dst = (which == 0) ? g_qb : (which == 1) ? g_kb : g_vb;
        if (which == 0) { a0 *= 0.125f; a1 *= 0.125f; }  // exact in bf16 (2^-3)
        unsigned pv = pack_bf16x2(a0, a1);
        *(unsigned*)(dst + ((size_t)(b * HH + h) * SS + s) * DH + d) = pv;
    } else if (EPI == EP_OPROJ) {
        size_t off = (size_t)r * DD + c;
        float2 res = *(const float2*)(g_x + off);
        float2 o = make_float2(v0 + bias[c] + res.x, v1 + bias[c + 1] + res.y);
        *(float2*)(g_y + off) = o;
    } else if (EPI == EP_FFN1) {
        unsigned pv = pack_bf16x2(fmaxf(v0 + bias[c], 0.f), fmaxf(v1 + bias[c + 1], 0.f));
        *(unsigned*)(g_h1b + (size_t)r * FF_ + c) = pv;
    } else if (EPI == EP_FFN2) {
        size_t off = (size_t)r * DD + c;
        float a0 = v0 + bias[c], a1 = v1 + bias[c + 1];
        *(float2*)(g_x + off) = make_float2(a0, a1);
        *(unsigned*)(g_xb + off) = pack_bf16x2(a0, a1);
    } else { // EP_HEAD
        if (c < VV)
            *(float2*)(outp + (size_t)r * VV + c) =
                make_float2(v0 + bias[c], v1 + bias[c + 1]);
    }
}

// ======================================================================
// bf16 mma.sync GEMM:  D[MT x NT] = A_tile @ B_tile^T  (fp32 accum)
// A: [M,K] bf16 K-major (lda).  B: [N,K] bf16 K-major (ldb).
// Grid: (N/NT, M/MT).  K multiple of 64.  BK=64, 3-stage cp.async,
// SINGLE __syncthreads per k-chunk, SW128 smem, ldmatrix.x4.
// Warp grid: WMC=MT/32 along M, warps/WMC along N.  Warp tile 32 x WN.
// NTHR in {256, 512}; occupancy hint 2 for 256-thread, 1 for 512-thread.
// ======================================================================
template<int EPI, int MT, int NT, int NTHR>
__global__ void __launch_bounds__(NTHR, (NTHR == 512) ? 1 : 2)
tgemm_k(const __nv_bfloat16* __restrict__ A, const __nv_bfloat16* __restrict__ B,
        int K, int lda, int ldb,
        const float* __restrict__ bias, float* __restrict__ outp)
{
    extern __shared__ char dsm[];
    constexpr int ABUF = MT * 128;
    constexpr int BBUF = NT * 128;
    constexpr int NWRP = NTHR / 32;
    constexpr int WMC  = MT / 32;        // warps along M
    constexpr int WNC  = NWRP / WMC;     // warps along N
    constexpr int WN   = NT / WNC;       // n-extent per warp
    constexpr int NTW  = WN / 8;         // 8-wide n-tiles per warp
    constexpr int AIT  = (MT * 8) / NTHR;
    constexpr int BIT  = (NT * 8) / NTHR;
    static_assert(WMC * WNC == NWRP && WN >= 16 && AIT >= 1 && BIT >= 1, "geom");

    const int tid  = threadIdx.x;
    const int lane = tid & 31, wid = tid >> 5;
    const int wm = wid % WMC, wn = wid / WMC;
    const int m0 = blockIdx.y * MT, n0 = blockIdx.x * NT;
    const unsigned sb = smem_u32(dsm);

    A += (size_t)m0 * lda;
    B += (size_t)n0 * ldb;

    const int NC = K >> 6;

    float acc[2][NTW][4];
#pragma unroll
    for (int i = 0; i < 2; i++)
#pragma unroll
        for (int j = 0; j < NTW; j++)
#pragma unroll
            for (int k = 0; k < 4; k++) acc[i][j][k] = 0.f;

    auto load_chunk = [&](int kc, int buf) {
        const __nv_bfloat16* Ap = A + kc * 64;
        unsigned ab = sb + buf * ABUF;
#pragma unroll
        for (int i = 0; i < AIT; i++) {
            int ch = tid + i * NTHR;
            int row = ch >> 3, c = ch & 7;
            CP_ASYNC16(ab + SWZ(row * 128 + c * 16), Ap + (size_t)row * lda + c * 8);
        }
        const __nv_bfloat16* Bp = B + kc * 64;
        unsigned bb = sb + 3 * ABUF + buf * BBUF;
#pragma unroll
        for (int i = 0; i < BIT; i++) {
            int ch = tid + i * NTHR;
            int row = ch >> 3, c = ch & 7;
            CP_ASYNC16(bb + SWZ(row * 128 + c * 16), Bp + (size_t)row * ldb + c * 8);
        }
    };

    load_chunk(0, 0); CP_COMMIT();
    if (NC > 1) load_chunk(1, 1);
    CP_COMMIT();

    const int a_row = (lane & 15);
    const int a_half = (lane >> 4);
    const int b_noff = (lane & 7) + ((lane >> 4) << 3);
    const int b_half = (lane >> 3) & 1;

    for (int kc = 0; kc < NC; kc++) {
        CP_WAIT1();            // groups retire in order -> chunk kc resident
        __syncthreads();       // all warps done reading stage (kc+2)%3
        if (kc + 2 < NC) load_chunk(kc + 2, (kc + 2) % 3);
        CP_COMMIT();

        const unsigned ab = sb + (kc % 3) * ABUF;
        const unsigned bb = sb + 3 * ABUF + (kc % 3) * BBUF;
#pragma unroll
        for (int ks = 0; ks < 4; ks++) {
            unsigned a[2][4];
#pragma unroll
            for (int mt = 0; mt < 2; mt++) {
                int row = wm * 32 + mt * 16 + a_row;
                LDSM4(a[mt], ab + SWZ(row * 128 + ks * 32 + a_half * 16));
            }
#pragma unroll
            for (int ntp = 0; ntp < NTW / 2; ntp++) {
                unsigned b[4];
                int nrow = wn * WN + ntp * 16 + b_noff;
                LDSM4(b, bb + SWZ(nrow * 128 + ks * 32 + b_half * 16));
#pragma unroll
                for (int mt = 0; mt < 2; mt++) {
                    MMA16816(acc[mt][2 * ntp],     a[mt], b[0], b[1]);
                    MMA16816(acc[mt][2 * ntp + 1], a[mt], b[2], b[3]);
                }
            }
        }
    }

    // ---- epilogue (paired stores: c0,c0+1) ----
    const int g = lane >> 2, t = lane & 3;
#pragma unroll
    for (int mt = 0; mt < 2; mt++) {
#pragma unroll
        for (int nt = 0; nt < NTW; nt++) {
            int r0 = m0 + wm * 32 + mt * 16 + g;
            int c0 = n0 + wn * WN + nt * 8 + t * 2;
            epi_store2<EPI>(r0,     c0, acc[mt][nt][0], acc[mt][nt][1], bias, outp);
            epi_store2<EPI>(r0 + 8, c0, acc[mt][nt][2], acc[mt][nt][3], bias, outp);
        }
    }
}

// ======================================================================
// Fused attention: per CTA one (b,h) and 128 query rows (8 warps x 16).
// Scale 1/8 pre-folded into q (exact).  S = Q' Kc^T, online softmax,
// O += P Vc.  V transpose via ldmatrix.x4.trans.  256 threads,
// K/V chunks of 128, double buffer.
// ======================================================================
__global__ void __launch_bounds__(256)
fattn_k()
{
    extern __shared__ char dsm[];
    const unsigned sb = smem_u32(dsm);
    const int tid = threadIdx.x, lane = tid & 31, w = tid >> 5;
    const int z = blockIdx.y;
    const int b = z / HH, h = z - b * HH;
    const int q0 = blockIdx.x * 128;

    const __nv_bfloat16* Q  = g_qb + (size_t)z * SS * DH + (size_t)q0 * DH;
    const __nv_bfloat16* Kp = g_kb + (size_t)z * SS * DH;
    const __nv_bfloat16* Vp = g_vb + (size_t)z * SS * DH;

    const unsigned QS = sb;                  // 16 KB (128 rows)
    const unsigned KS = sb + 16384;          // 2 x 16 KB
    const unsigned VS = sb + 16384 + 32768;  // 2 x 16 KB

#pragma unroll
    for (int i = 0; i < 4; i++) {
        int ch = tid + i * 256, row = ch >> 3, c = ch & 7;
        CP_ASYNC16(QS + SWZ(row * 128 + c * 16), Q + (size_t)row * DH + c * 8);
    }
    auto loadKV = [&](int kc, int buf) {
        const __nv_bfloat16* Kc = Kp + (size_t)(kc * 128) * DH;
        unsigned kb = KS + buf * 16384;
#pragma unroll
        for (int i = 0; i < 4; i++) {
            int ch = tid + i * 256, row = ch >> 3, c = ch & 7;
            CP_ASYNC16(kb + SWZ(row * 128 + c * 16), Kc + (size_t)row * DH + c * 8);
        }
        const __nv_bfloat16* Vc = Vp + (size_t)(kc * 128) * DH;
        unsigned vb = VS + buf * 16384;
#pragma unroll
        for (int i = 0; i < 4; i++) {
            int ch = tid + i * 256, row = ch >> 3, c = ch & 7;
            CP_ASYNC16(vb + SWZ(row * 128 + c * 16), Vc + (size_t)row * DH + c * 8);
        }
    };
    loadKV(0, 0); CP_COMMIT();
    loadKV(1, 1); CP_COMMIT();

    float oacc[8][4];
#pragma unroll
    for (int j = 0; j < 8; j++)
#pragma unroll
        for (int k = 0; k < 4; k++) oacc[j][k] = 0.f;
    float m0 = -1e30f, m1 = -1e30f, l0 = 0.f, l1 = 0.f;

    const int a_row = (lane & 15), a_half = (lane >> 4);
    const int b_noff = (lane & 7) + ((lane >> 4) << 3), b_half = (lane >> 3) & 1;
    const int g = lane >> 2, t4 = lane & 3;
    const int v_row = (lane & 7) + ((lane >> 3) & 1) * 8;
    const int v_col = (lane >> 4) * 16;

    for (int kc = 0; kc < 4; kc++) {
        if (kc < 3) CP_WAIT1(); else CP_WAIT0();
        __syncthreads();
        const unsigned kb = KS + (kc & 1) * 16384;
        const unsigned vb = VS + (kc & 1) * 16384;

        float sacc[16][4];
#pragma unroll
        for (int j = 0; j < 16; j++)
#pragma unroll
            for (int k = 0; k < 4; k++) sacc[j][k] = 0.f;
#pragma unroll
        for (int ks = 0; ks < 4; ks++) {
            unsigned aq[4];
            LDSM4(aq, QS + SWZ((w * 16 + a_row) * 128 + ks * 32 + a_half * 16));
#pragma unroll
            for (int ntp = 0; ntp < 8; ntp++) {
                unsigned bk[4];
                LDSM4(bk, kb + SWZ((ntp * 16 + b_noff) * 128 + ks * 32 + b_half * 16));
                MMA16816(sacc[2 * ntp],     aq, bk[0], bk[1]);
                MMA16816(sacc[2 * ntp + 1], aq, bk[2], bk[3]);
            }
        }
        // ---- online softmax (scale already folded into q) ----
        float mx0 = -1e30f, mx1 = -1e30f;
#pragma unroll
        for (int j = 0; j < 16; j++) {
            mx0 = fmaxf(mx0, fmaxf(sacc[j][0], sacc[j][1]));
            mx1 = fmaxf(mx1, fmaxf(sacc[j][2], sacc[j][3]));
        }
        mx0 = fmaxf(mx0, __shfl_xor_sync(0xffffffffu, mx0, 1));
        mx0 = fmaxf(mx0, __shfl_xor_sync(0xffffffffu, mx0, 2));
        mx1 = fmaxf(mx1, __shfl_xor_sync(0xffffffffu, mx1, 1));
        mx1 = fmaxf(mx1, __shfl_xor_sync(0xffffffffu, mx1, 2));
        float nm0 = fmaxf(m0, mx0), nm1 = fmaxf(m1, mx1);
        float al0 = expf(m0 - nm0), al1 = expf(m1 - nm1);
        m0 = nm0; m1 = nm1;
        float rs0 = 0.f, rs1 = 0.f;
#pragma unroll
        for (int j = 0; j < 16; j++) {
            sacc[j][0] = expf(sacc[j][0] - m0); sacc[j][1] = expf(sacc[j][1] - m0);
            sacc[j][2] = expf(sacc[j][2] - m1); sacc[j][3] = expf(sacc[j][3] - m1);
            rs0 += sacc[j][0] + sacc[j][1];
            rs1 += sacc[j][2] + sacc[j][3];
        }
        rs0 += __shfl_xor_sync(0xffffffffu, rs0, 1);
        rs0 += __shfl_xor_sync(0xffffffffu, rs0, 2);
        rs1 += __shfl_xor_sync(0xffffffffu, rs1, 1);
        rs1 += __shfl_xor_sync(0xffffffffu, rs1, 2);
        l0 = l0 * al0 + rs0;
        l1 = l1 * al1 + rs1;
#pragma unroll
        for (int j = 0; j < 8; j++) {
            oacc[j][0] *= al0; oacc[j][1] *= al0;
            oacc[j][2] *= al1; oacc[j][3] *= al1;
        }
#pragma unroll
        for (int ksl = 0; ksl < 8; ksl++) {
            unsigned pa[4];
            pa[0] = pack_bf16x2(sacc[2 * ksl][0],     sacc[2 * ksl][1]);
            pa[1] = pack_bf16x2(sacc[2 * ksl][2],     sacc[2 * ksl][3]);
            pa[2] = pack_bf16x2(sacc[2 * ksl + 1][0], sacc[2 * ksl + 1][1]);
            pa[3] = pack_bf16x2(sacc[2 * ksl + 1][2], sacc[2 * ksl + 1][3]);
#pragma unroll
            for (int ntp = 0; ntp < 4; ntp++) {
                unsigned bv[4];
                LDSM4T(bv, vb + SWZ((ksl * 16 + v_row) * 128 + ntp * 32 + v_col));
                MMA16816(oacc[2 * ntp],     pa, bv[0], bv[1]);
                MMA16816(oacc[2 * ntp + 1], pa, bv[2], bv[3]);
            }
        }
        __syncthreads();
        if (kc + 2 < 4) { loadKV(kc + 2, kc & 1); CP_COMMIT(); }
    }

    float inv0 = 1.f / l0, inv1 = 1.f / l1;
    int row0 = q0 + w * 16 + g;
    __nv_bfloat16* Ob = g_ob + (size_t)(b * SS) * DD + h * DH;
#pragma unroll
    for (int j = 0; j < 8; j++) {
        int col = j * 8 + t4 * 2;
        *(__nv_bfloat162*)(Ob + (size_t)row0 * DD + col) =
            __float22bfloat162_rn(make_float2(oacc[j][0] * inv0, oacc[j][1] * inv0));
        *(__nv_bfloat162*)(Ob + (size_t)(row0 + 8) * DD + col) =
            __float22bfloat162_rn(make_float2(oacc[j][2] * inv1, oacc[j][3] * inv1));
    }
}

// ======================================================================
// weight transpose+pack: src fp32 [K,N] -> dst bf16 [Npad,K] (64x64 tiles)
// ======================================================================
__global__ void __launch_bounds__(256)
packT_k(const float* __restrict__ src, __nv_bfloat16* __restrict__ dst,
        int K, int N, int Npad)
{
    __shared__ float ts[64][65];
    int n0 = blockIdx.x * 64, k0 = blockIdx.y * 64;
    int t = threadIdx.x;
    int kr = t >> 2, cq = t & 3;
#pragma unroll
    for (int i = 0; i < 4; i++) {
        int nc = (cq + i * 4) * 4;
        int n = n0 + nc;
        const float* sp = src + (size_t)(k0 + kr) * N;
        float4 v;
        if (n + 3 < N) v = *(const float4*)(sp + n);
        else {
            v.x = (n + 0 < N) ? sp[n + 0] : 0.f;
            v.y = (n + 1 < N) ? sp[n + 1] : 0.f;
            v.z = (n + 2 < N) ? sp[n + 2] : 0.f;
            v.w = (n + 3 < N) ? sp[n + 3] : 0.f;
        }
        ts[kr][nc] = v.x; ts[kr][nc + 1] = v.y; ts[kr][nc + 2] = v.z; ts[kr][nc + 3] = v.w;
    }
    __syncthreads();
    int nr = t >> 2, ks = (t & 3) * 16;
    if (n0 + nr < Npad) {
        unsigned ov[8];
#pragma unroll
        for (int e = 0; e < 8; e++)
            ov[e] = pack_bf16x2(ts[ks + 2 * e][nr], ts[ks + 2 * e + 1][nr]);
        __nv_bfloat16* dp = dst + (size_t)(n0 + nr) * K + k0 + ks;
        *(uint4*)dp       = make_uint4(ov[0], ov[1], ov[2], ov[3]);
        *(uint4*)(dp + 8) = make_uint4(ov[4], ov[5], ov[6], ov[7]);
    }
}

__global__ void packb_k(const float* __restrict__ bq, const float* __restrict__ bk,
                        const float* __restrict__ bv, float* __restrict__ dst)
{
    int i = blockIdx.x * 256 + threadIdx.x;
    if (i < DD) dst[i] = bq[i];
    else if (i < 2 * DD) dst[i] = bk[i - DD];
    else if (i < 3 * DD) dst[i] = bv[i - 2 * DD];
}

// ======================================================================
// one-hot -> token id (float4 scan, block-wide early exit)
// ======================================================================
__global__ void findtok_k(const float* __restrict__ oh, int* __restrict__ tok)
{
    __shared__ int found;
    size_t row = blockIdx.x;
    const float4* r = (const float4*)(oh + row * (size_t)VV);
    int t = threadIdx.x;
    if (t == 0) found = 0;
    __syncthreads();
    const int NQ = VV / 4;                  // 7500
    for (int j = t; j < NQ; j += 256) {
        float4 v = r[j];
        if (v.x > 0.5f || v.y > 0.5f || v.z > 0.5f || v.w > 0.5f) {
            int o = (v.x > 0.5f) ? 0 : (v.y > 0.5f) ? 1 : (v.z > 0.5f) ? 2 : 3;
            tok[row] = 4 * j + o;
            found = 1;
        }
        __syncthreads();
        if (found) break;
        __syncthreads();
    }
}

// ======================================================================
// x = se_w[tok] + se_b + positional encoding ; also bf16 mirror
// ======================================================================
__global__ void embed_k(const float* __restrict__ se_w, const float* __restrict__ se_b,
                        const int* __restrict__ tok, float* __restrict__ x,
                        __nv_bfloat16* __restrict__ xb)
{
    int row = blockIdx.x;
    int s   = row & (SS - 1);
    int tk  = tok[row];
    const float* wrow = se_w + (size_t)tk * DD;
    float* xr = x + (size_t)row * DD;
    __nv_bfloat16* xbr = xb + (size_t)row * DD;
    for (int d = threadIdx.x; d < DD; d += blockDim.x) {
        float pe = 0.f;
        if (s != 0) {
            float denom = powf(10000.0f, (2.0f * (float)d) / (float)DD);
            float raw   = (float)s / denom;
            pe = (d & 1) ? cosf(raw) : sinf(raw);
        }
        float v = wrow[d] + se_b[d] + pe;
        xr[d] = v;
        xbr[d] = __float2bfloat16(v);
    }
}

// ======================================================================
// layernorm over D=768 (fp32 in -> bf16 out)
// ======================================================================
__global__ void layernorm_k(const float* __restrict__ y, __nv_bfloat16* __restrict__ x)
{
    __shared__ float rs[8], rq[8];
    size_t row = blockIdx.x;
    const float* yp = y + row * DD;
    __nv_bfloat16* xp = x + row * DD;
    int t = threadIdx.x;
    float a0 = yp[t], a1 = yp[t + 256], a2 = yp[t + 512];
    float s = a0 + a1 + a2;
    float q = a0 * a0 + a1 * a1 + a2 * a2;
#pragma unroll
    for (int o = 16; o; o >>= 1) {
        s += __shfl_xor_sync(0xffffffffu, s, o);
        q += __shfl_xor_sync(0xffffffffu, q, o);
    }
    if ((t & 31) == 0) { rs[t >> 5] = s; rq[t >> 5] = q; }
    __syncthreads();
    s = rs[0] + rs[1] + rs[2] + rs[3] + rs[4] + rs[5] + rs[6] + rs[7];
    q = rq[0] + rq[1] + rq[2] + rq[3] + rq[4] + rq[5] + rq[6] + rq[7];
    float mean = s * (1.0f / (float)DD);
    float var  = q * (1.0f / (float)DD) - mean * mean;
    float r = rsqrtf(var + 1e-5f);
    xp[t]       = __float2bfloat16((a0 - mean) * r);
    xp[t + 256] = __float2bfloat16((a1 - mean) * r);
    xp[t + 512] = __float2bfloat16((a2 - mean) * r);
}

// ======================================================================
// gather masked rows (bf16 -> bf16)
// ======================================================================
__global__ void gather_k(const __nv_bfloat16* __restrict__ x, const int* __restrict__ idx,
                         __nv_bfloat16* __restrict__ g)
{
    int r = blockIdx.x;
    int b = r >> 6;
    int s = idx[r];
    const __nv_bfloat16* src = x + ((size_t)(b * SS + s)) * DD;
    __nv_bfloat16* dst = g + (size_t)r * DD;
    for (int d = threadIdx.x; d < DD; d += blockDim.x) dst[d] = src[d];
}

// ======================================================================
// in-place log_softmax over V=30000 — single gmem read via smem staging
// ======================================================================
__global__ void logsoftmax_k(float* __restrict__ out)
{
    extern __shared__ float buf[];       // 30000 floats = 117.2 KB
    __shared__ float red[8];
    size_t row = blockIdx.x;
    float* p = out + row * (size_t)VV;
    int t = threadIdx.x;

    float m = -1e30f;
    for (int j = t; j < VV / 4; j += 256) {
        float4 v = *(const float4*)(p + 4 * j);
        *(float4*)(buf + 4 * j) = v;
        m = fmaxf(fmaxf(m, fmaxf(v.x, v.y)), fmaxf(v.z, v.w));
    }
#pragma unroll
    for (int o = 16; o; o >>= 1) m = fmaxf(m, __shfl_xor_sync(0xffffffffu, m, o));
    if ((t & 31) == 0) red[t >> 5] = m;
    __syncthreads();
    m = fmaxf(fmaxf(fmaxf(red[0], red[1]), fmaxf(red[2], red[3])),
              fmaxf(fmaxf(red[4], red[5]), fmaxf(red[6], red[7])));

    float s = 0.f;
    for (int j = t; j < VV / 4; j += 256) {
        float4 v = *(const float4*)(buf + 4 * j);
        s += expf(v.x - m) + expf(v.y - m) + expf(v.z - m) + expf(v.w - m);
    }
#pragma unroll
    for (int o = 16; o; o >>= 1) s += __shfl_xor_sync(0xffffffffu, s, o);
    __syncthreads();
    if ((t & 31) == 0) red[t >> 5] = s;
    __syncthreads();
    s = red[0] + red[1] + red[2] + red[3] + red[4] + red[5] + red[6] + red[7];

    float lse = m + logf(s);
    for (int j = t; j < VV / 4; j += 256) {
        float4 v = *(const float4*)(buf + 4 * j);
        *(float4*)(p + 4 * j) = make_float4(v.x - lse, v.y - lse, v.z - lse, v.w - lse);
    }
}

// ======================================================================
// launcher
// ======================================================================
extern "C" void kernel_launch(void* const* d_in, const int* in_sizes, int n_in,
                              void* d_out, int out_size)
{
    (void)in_sizes; (void)n_in; (void)out_size;
    const float* onehot = (const float*)d_in[0];
    const float* se_w = (const float*)d_in[1];
    const float* se_b = (const float*)d_in[2];
    const float* wq = (const float*)d_in[3];  const float* bq = (const float*)d_in[4];
    const float* wk = (const float*)d_in[5];  const float* bk = (const float*)d_in[6];
    const float* wv = (const float*)d_in[7];  const float* bv = (const float*)d_in[8];
    const float* wo = (const float*)d_in[9];  const float* bo = (const float*)d_in[10];
    const float* w1 = (const float*)d_in[11]; const float* b1 = (const float*)d_in[12];
    const float* w2 = (const float*)d_in[13]; const float* b2 = (const float*)d_in[14];
    const float* we = (const float*)d_in[15]; const float* be = (const float*)d_in[16];
    const int*   idx = (const int*)d_in[17];
    float* out = (float*)d_out;

    float *px, *py, *pbqkv;
    __nv_bfloat16 *pxb, *plnb, *pob, *ph1b, *pgb;
    __nv_bfloat16 *pwqkv, *pwow, *pw1w, *pw2w, *pwew;
    int* ptok;
    cudaGetSymbolAddress((void**)&px,    g_x);
    cudaGetSymbolAddress((void**)&py,    g_y);
    cudaGetSymbolAddress((void**)&pbqkv, g_bqkv);
    cudaGetSymbolAddress((void**)&pxb,   g_xb);
    cudaGetSymbolAddress((void**)&plnb,  g_lnb);
    cudaGetSymbolAddress((void**)&pob,   g_ob);
    cudaGetSymbolAddress((void**)&ph1b,  g_h1b);
    cudaGetSymbolAddress((void**)&pgb,   g_gb);
    cudaGetSymbolAddress((void**)&pwqkv, g_wqkv);
    cudaGetSymbolAddress((void**)&pwow,  g_wow);
    cudaGetSymbolAddress((void**)&pw1w,  g_w1w);
    cudaGetSymbolAddress((void**)&pw2w,  g_w2w);
    cudaGetSymbolAddress((void**)&pwew,  g_wew);
    cudaGetSymbolAddress((void**)&ptok,  g_tok);

    const int SMWIDE = 3 * (16384 + 32768);   // 147456: MT=128,NT=256
    const int SMG128 = 3 * (16384 + 16384);   // 98304:  MT=128,NT=128
    const int SMG64  = 3 * (8192 + 16384);    // 73728:  MT=64, NT=128
    const int SMA = 16384 + 32768 + 32768;    // 81920
    const int SML = VV * 4;                   // 120000
    cudaFuncSetAttribute((const void*)tgemm_k<EP_QKV,  128, 256, 512>,
                         cudaFuncAttributeMaxDynamicSharedMemorySize, SMWIDE);
    cudaFuncSetAttribute((const void*)tgemm_k<EP_FFN1, 128, 256, 512>,
                         cudaFuncAttributeMaxDynamicSharedMemorySize, SMWIDE);
    cudaFuncSetAttribute((const void*)tgemm_k<EP_OPROJ, 64, 128, 256>,
                         cudaFuncAttributeMaxDynamicSharedMemorySize, SMG64);
    cudaFuncSetAttribute((const void*)tgemm_k<EP_FFN2,  64, 128, 256>,
                         cudaFuncAttributeMaxDynamicSharedMemorySize, SMG64);
    cudaFuncSetAttribute((const void*)tgemm_k<EP_HEAD, 128, 128, 256>,
                         cudaFuncAttributeMaxDynamicSharedMemorySize, SMG128);
    cudaFuncSetAttribute((const void*)fattn_k,
                         cudaFuncAttributeMaxDynamicSharedMemorySize, SMA);
    cudaFuncSetAttribute((const void*)logsoftmax_k,
                         cudaFuncAttributeMaxDynamicSharedMemorySize, SML);

    // ---- stream fork: weight packs overlap the one-hot scan/embedding ----
    static cudaStream_t sPack = nullptr;
    static cudaEvent_t  evFork = nullptr, evJoin = nullptr;
    if (sPack == nullptr) {
        if (cudaStreamCreateWithFlags(&sPack, cudaStreamNonBlocking) != cudaSuccess)
            sPack = nullptr;
        if (sPack) {
            cudaEventCreateWithFlags(&evFork, cudaEventDisableTiming);
            cudaEventCreateWithFlags(&evJoin, cudaEventDisableTiming);
        }
    }
    cudaStream_t sp = sPack ? sPack : (cudaStream_t)0;
    if (sPack) {
        cudaEventRecord(evFork, 0);
        cudaStreamWaitEvent(sPack, evFork, 0);
    }

    // ---- weight/bias packing (bf16, [N,K]) on side stream ----
    packb_k<<<9, 256, 0, sp>>>(bq, bk, bv, pbqkv);
    packT_k<<<dim3(12, 12), 256, 0, sp>>>(wq, pwqkv,               DD, DD, DD);
    packT_k<<<dim3(12, 12), 256, 0, sp>>>(wk, pwqkv + DD * DD,     DD, DD, DD);
    packT_k<<<dim3(12, 12), 256, 0, sp>>>(wv, pwqkv + 2 * DD * DD, DD, DD, DD);
    packT_k<<<dim3(12, 12), 256, 0, sp>>>(wo, pwow,                DD, DD, DD);
    packT_k<<<dim3(48, 12), 256, 0, sp>>>(w1, pw1w,                DD, FF_, FF_);
    packT_k<<<dim3(12, 48), 256, 0, sp>>>(w2, pw2w,                FF_, DD, DD);
    packT_k<<<dim3(470, 12), 256, 0, sp>>>(we, pwew,               DD, VV, VPAD);
    if (sPack) cudaEventRecord(evJoin, sPack);

    // ---- embedding on default stream (concurrent with packs) ----
    findtok_k<<<BB * SS, 256>>>(onehot, ptok);
    embed_k<<<BB * SS, 256>>>(se_w, se_b, ptok, px, pxb);

    if (sPack) cudaStreamWaitEvent((cudaStream_t)0, evJoin, 0);

    for (int l = 0; l < NLAYERS; l++) {
        // QKV fused: [2048,768] @ [2304,768]^T -> per-head q/k/v (bf16)
        // 128x256 tiles, 512 threads -> 144 CTAs = one full wave
        tgemm_k<EP_QKV, 128, 256, 512><<<dim3(9, 16), 512, SMWIDE>>>(
            pxb, pwqkv, DD, DD, DD, pbqkv, nullptr);

        // fused attention -> g_ob (bf16, heads concatenated)
        fattn_k<<<dim3(SS / 128, BB * HH), 256, SMA>>>();

        // o @ wo + bo + x -> y (fp32)   [64x128 tiles -> 192 CTAs]
        tgemm_k<EP_OPROJ, 64, 128, 256><<<dim3(6, 32), 256, SMG64>>>(
            pob, pwow, DD, DD, DD, bo, nullptr);

        layernorm_k<<<BB * SS, 256>>>(py, plnb);

        // relu(ln @ w1 + b1) -> h1b (bf16)   [128x256 tiles -> 192 CTAs]
        tgemm_k<EP_FFN1, 128, 256, 512><<<dim3(12, 16), 512, SMWIDE>>>(
            plnb, pw1w, DD, DD, DD, b1, nullptr);

        // h1 @ w2 + b2 -> x (fp32) + xb (bf16)   [64x128 tiles -> 192 CTAs]
        tgemm_k<EP_FFN2, 64, 128, 256><<<dim3(6, 32), 256, SMG64>>>(
            ph1b, pw2w, FF_, FF_, FF_, b2, nullptr);
    }

    // gather + vocab head + log_softmax
    gather_k<<<BB * MM, 256>>>(pxb, idx, pgb);
    tgemm_k<EP_HEAD, 128, 128, 256><<<dim3(VPAD / 128, 2), 256, SMG128>>>(
        pgb, pwew, DD, DD, DD, be, out);
    logsoftmax_k<<<BB * MM, 256, SML>>>(out);
}

// round 17
// speedup vs baseline: 1.0593x; 1.0593x over previous
#include <cuda_runtime.h>
#include <cuda_bf16.h>
#include <math.h>

// ---------------- problem constants ----------------
#define BB 4
#define SS 512
#define DD 768
#define FF_ 3072
#define VV 30000
#define VPAD 30080
#define HH 12
#define MM 64
#define DH 64
#define NLAYERS 12

// ---------------- static device scratch ----------------
__device__ float g_x  [BB*SS*DD];
__device__ float g_y  [BB*SS*DD];
__device__ float g_bqkv[3*DD];
__device__ __nv_bfloat16 g_xb  [BB*SS*DD];
__device__ __nv_bfloat16 g_lnb [BB*SS*DD];
__device__ __nv_bfloat16 g_ob  [BB*SS*DD];
__device__ __nv_bfloat16 g_qb  [BB*HH*SS*DH];
__device__ __nv_bfloat16 g_kb  [BB*HH*SS*DH];
__device__ __nv_bfloat16 g_vb  [BB*HH*SS*DH];
__device__ __nv_bfloat16 g_h1b [BB*SS*FF_];
__device__ __nv_bfloat16 g_gb  [BB*MM*DD];
__device__ __nv_bfloat16 g_wqkv[3*DD*DD];   // [n=2304][k=768]
__device__ __nv_bfloat16 g_wow [DD*DD];     // [n][k]
__device__ __nv_bfloat16 g_w1w [FF_*DD];    // [3072][768]
__device__ __nv_bfloat16 g_w2w [DD*FF_];    // [768][3072]
__device__ __nv_bfloat16 g_wew [VPAD*DD];   // [30080][768], rows >= 30000 zero
__device__ int g_tok[BB*SS];

// ====================== PTX helpers (arch-portable) ====================
__device__ __forceinline__ unsigned smem_u32(const void* p) {
    unsigned a;
    asm("{ .reg .u64 t; cvta.to.shared.u64 t, %1; cvt.u32.u64 %0, t; }" : "=r"(a) : "l"(p));
    return a;
}
#define SWZ(off) ((unsigned)(off) ^ (((unsigned)(off) >> 3) & 0x70u))

#define CP_ASYNC16(dst, src) \
    asm volatile("cp.async.cg.shared.global [%0], [%1], 16;" :: "r"(dst), "l"(src))
#define CP_COMMIT() asm volatile("cp.async.commit_group;" ::: "memory")
#define CP_WAIT1()  asm volatile("cp.async.wait_group 1;" ::: "memory")
#define CP_WAIT0()  asm volatile("cp.async.wait_group 0;" ::: "memory")

#define LDSM4(r, addr) \
    asm volatile("ldmatrix.sync.aligned.m8n8.x4.shared.b16 {%0,%1,%2,%3}, [%4];" \
        : "=r"((r)[0]), "=r"((r)[1]), "=r"((r)[2]), "=r"((r)[3]) : "r"(addr))

#define LDSM4T(r, addr) \
    asm volatile("ldmatrix.sync.aligned.m8n8.x4.trans.shared.b16 {%0,%1,%2,%3}, [%4];" \
        : "=r"((r)[0]), "=r"((r)[1]), "=r"((r)[2]), "=r"((r)[3]) : "r"(addr))

#define MMA16816(c, a, b0, b1) \
    asm volatile("mma.sync.aligned.m16n8k16.row.col.f32.bf16.bf16.f32 " \
        "{%0,%1,%2,%3}, {%4,%5,%6,%7}, {%8,%9}, {%0,%1,%2,%3};" \
        : "+f"((c)[0]), "+f"((c)[1]), "+f"((c)[2]), "+f"((c)[3]) \
        : "r"((a)[0]), "r"((a)[1]), "r"((a)[2]), "r"((a)[3]), "r"(b0), "r"(b1))

__device__ __forceinline__ unsigned pack_bf16x2(float lo, float hi) {
    __nv_bfloat162 h = __float22bfloat162_rn(make_float2(lo, hi));
    return *(unsigned*)&h;
}

// ---------------- epilogue modes ----------------
#define EP_QKV   0
#define EP_OPROJ 1
#define EP_FFN1  2
#define EP_FFN2  3
#define EP_HEAD  4

// paired store: columns (c, c+1), c even, same row r
template<int EPI>
__device__ __forceinline__ void epi_store2(int r, int c, float v0, float v1,
                                           const float* __restrict__ bias,
                                           float* __restrict__ outp)
{
    if (EPI == EP_QKV) {
        int b = r >> 9, s = r & 511;
        float a0 = v0 + bias[c], a1 = v1 + bias[c + 1];
        int which = c / DD, rr = c - which * DD, h = rr >> 6, d = rr & 63;
        __nv_bfloat16* dst = (which == 0) ? g_qb : (which == 1) ? g_kb : g_vb;
        if (which == 0) { a0 *= 0.125f; a1 *= 0.125f; }  // exact (2^-3, exponent-only)
        unsigned pv = pack_bf16x2(a0, a1);
        *(unsigned*)(dst + ((size_t)(b * HH + h) * SS + s) * DH + d) = pv;
    } else if (EPI == EP_OPROJ) {
        size_t off = (size_t)r * DD + c;
        float2 res = *(const float2*)(g_x + off);
        float2 o = make_float2(v0 + bias[c] + res.x, v1 + bias[c + 1] + res.y);
        *(float2*)(g_y + off) = o;
    } else if (EPI == EP_FFN1) {
        unsigned pv = pack_bf16x2(fmaxf(v0 + bias[c], 0.f), fmaxf(v1 + bias[c + 1], 0.f));
        *(unsigned*)(g_h1b + (size_t)r * FF_ + c) = pv;
    } else if (EPI == EP_FFN2) {
        size_t off = (size_t)r * DD + c;
        float a0 = v0 + bias[c], a1 = v1 + bias[c + 1];
        *(float2*)(g_x + off) = make_float2(a0, a1);
        *(unsigned*)(g_xb + off) = pack_bf16x2(a0, a1);
    } else { // EP_HEAD
        if (c < VV)
            *(float2*)(outp + (size_t)r * VV + c) =
                make_float2(v0 + bias[c], v1 + bias[c + 1]);
    }
}

// ======================================================================
// bf16 mma.sync GEMM:  D[MT x 128] = A_tile @ B_tile^T  (fp32 accum)
// A: [M,K] bf16 K-major (lda).  B: [N,K] bf16 K-major (ldb).
// Grid: (N/128, M/MT).  K multiple of 64.  BK=64, 3-stage cp.async,
// SINGLE __syncthreads per k-chunk, SW128 smem, ldmatrix.x4.
// MT in {64,128}.  256 threads; OCC = min-CTAs-per-SM hint.
// ======================================================================
template<int EPI, int MT, int OCC>
__global__ void __launch_bounds__(256, OCC)
tgemm_k(const __nv_bfloat16* __restrict__ A, const __nv_bfloat16* __restrict__ B,
        int K, int lda, int ldb,
        const float* __restrict__ bias, float* __restrict__ outp)
{
    extern __shared__ char dsm[];
    constexpr int ABUF = MT * 128;
    constexpr int BBUF = 128 * 128;
    constexpr int WMC  = MT / 32;        // warps along M
    constexpr int WNC  = 8 / WMC;        // warps along N
    constexpr int WN   = 128 / WNC;      // n-extent per warp
    constexpr int NTW  = WN / 8;         // 8-wide n-tiles per warp

    const int tid  = threadIdx.x;
    const int lane = tid & 31, wid = tid >> 5;
    const int wm = wid % WMC, wn = wid / WMC;
    const int m0 = blockIdx.y * MT, n0 = blockIdx.x * 128;
    const unsigned sb = smem_u32(dsm);

    A += (size_t)m0 * lda;
    B += (size_t)n0 * ldb;

    const int NC = K >> 6;

    float acc[2][NTW][4];
#pragma unroll
    for (int i = 0; i < 2; i++)
#pragma unroll
        for (int j = 0; j < NTW; j++)
#pragma unroll
            for (int k = 0; k < 4; k++) acc[i][j][k] = 0.f;

    auto load_chunk = [&](int kc, int buf) {
        const __nv_bfloat16* Ap = A + kc * 64;
        unsigned ab = sb + buf * ABUF;
#pragma unroll
        for (int i = 0; i < MT / 32; i++) {
            int ch = tid + i * 256;
            int row = ch >> 3, c = ch & 7;
            CP_ASYNC16(ab + SWZ(row * 128 + c * 16), Ap + (size_t)row * lda + c * 8);
        }
        const __nv_bfloat16* Bp = B + kc * 64;
        unsigned bb = sb + 3 * ABUF + buf * BBUF;
#pragma unroll
        for (int i = 0; i < 4; i++) {
            int ch = tid + i * 256;
            int row = ch >> 3, c = ch & 7;
            CP_ASYNC16(bb + SWZ(row * 128 + c * 16), Bp + (size_t)row * ldb + c * 8);
        }
    };

    load_chunk(0, 0); CP_COMMIT();
    if (NC > 1) load_chunk(1, 1);
    CP_COMMIT();

    const int a_row = (lane & 15);
    const int a_half = (lane >> 4);
    const int b_noff = (lane & 7) + ((lane >> 4) << 3);
    const int b_half = (lane >> 3) & 1;

    for (int kc = 0; kc < NC; kc++) {
        CP_WAIT1();            // groups retire in order -> chunk kc resident
        __syncthreads();       // all warps done reading stage (kc+2)%3
        if (kc + 2 < NC) load_chunk(kc + 2, (kc + 2) % 3);
        CP_COMMIT();

        const unsigned ab = sb + (kc % 3) * ABUF;
        const unsigned bb = sb + 3 * ABUF + (kc % 3) * BBUF;
#pragma unroll
        for (int ks = 0; ks < 4; ks++) {
            unsigned a[2][4];
#pragma unroll
            for (int mt = 0; mt < 2; mt++) {
                int row = wm * 32 + mt * 16 + a_row;
                LDSM4(a[mt], ab + SWZ(row * 128 + ks * 32 + a_half * 16));
            }
#pragma unroll
            for (int ntp = 0; ntp < NTW / 2; ntp++) {
                unsigned b[4];
                int nrow = wn * WN + ntp * 16 + b_noff;
                LDSM4(b, bb + SWZ(nrow * 128 + ks * 32 + b_half * 16));
#pragma unroll
                for (int mt = 0; mt < 2; mt++) {
                    MMA16816(acc[mt][2 * ntp],     a[mt], b[0], b[1]);
                    MMA16816(acc[mt][2 * ntp + 1], a[mt], b[2], b[3]);
                }
            }
        }
    }

    // ---- epilogue (paired stores: c0,c0+1) ----
    const int g = lane >> 2, t = lane & 3;
#pragma unroll
    for (int mt = 0; mt < 2; mt++) {
#pragma unroll
        for (int nt = 0; nt < NTW; nt++) {
            int r0 = m0 + wm * 32 + mt * 16 + g;
            int c0 = n0 + wn * WN + nt * 8 + t * 2;
            epi_store2<EPI>(r0,     c0, acc[mt][nt][0], acc[mt][nt][1], bias, outp);
            epi_store2<EPI>(r0 + 8, c0, acc[mt][nt][2], acc[mt][nt][3], bias, outp);
        }
    }
}

// ======================================================================
// Fused attention: per CTA one (b,h) and 128 query rows (8 warps x 16).
// Scale 1/8 pre-folded into q (exact).  S = Q' Kc^T, online softmax,
// O += P Vc.  V transpose via ldmatrix.x4.trans.  256 threads,
// K/V chunks of 128, double buffer (two-sync structure).
// ======================================================================
__global__ void __launch_bounds__(256)
fattn_k()
{
    extern __shared__ char dsm[];
    const unsigned sb = smem_u32(dsm);
    const int tid = threadIdx.x, lane = tid & 31, w = tid >> 5;
    const int z = blockIdx.y;
    const int b = z / HH, h = z - b * HH;
    const int q0 = blockIdx.x * 128;

    const __nv_bfloat16* Q  = g_qb + (size_t)z * SS * DH + (size_t)q0 * DH;
    const __nv_bfloat16* Kp = g_kb + (size_t)z * SS * DH;
    const __nv_bfloat16* Vp = g_vb + (size_t)z * SS * DH;

    const unsigned QS = sb;                  // 16 KB (128 rows)
    const unsigned KS = sb + 16384;          // 2 x 16 KB
    const unsigned VS = sb + 16384 + 32768;  // 2 x 16 KB

#pragma unroll
    for (int i = 0; i < 4; i++) {
        int ch = tid + i * 256, row = ch >> 3, c = ch & 7;
        CP_ASYNC16(QS + SWZ(row * 128 + c * 16), Q + (size_t)row * DH + c * 8);
    }
    auto loadKV = [&](int kc, int buf) {
        const __nv_bfloat16* Kc = Kp + (size_t)(kc * 128) * DH;
        unsigned kb = KS + buf * 16384;
#pragma unroll
        for (int i = 0; i < 4; i++) {
            int ch = tid + i * 256, row = ch >> 3, c = ch & 7;
            CP_ASYNC16(kb + SWZ(row * 128 + c * 16), Kc + (size_t)row * DH + c * 8);
        }
        const __nv_bfloat16* Vc = Vp + (size_t)(kc * 128) * DH;
        unsigned vb = VS + buf * 16384;
#pragma unroll
        for (int i = 0; i < 4; i++) {
            int ch = tid + i * 256, row = ch >> 3, c = ch & 7;
            CP_ASYNC16(vb + SWZ(row * 128 + c * 16), Vc + (size_t)row * DH + c * 8);
        }
    };
    loadKV(0, 0); CP_COMMIT();
    loadKV(1, 1); CP_COMMIT();

    float oacc[8][4];
#pragma unroll
    for (int j = 0; j < 8; j++)
#pragma unroll
        for (int k = 0; k < 4; k++) oacc[j][k] = 0.f;
    float m0 = -1e30f, m1 = -1e30f, l0 = 0.f, l1 = 0.f;

    const int a_row = (lane & 15), a_half = (lane >> 4);
    const int b_noff = (lane & 7) + ((lane >> 4) << 3), b_half = (lane >> 3) & 1;
    const int g = lane >> 2, t4 = lane & 3;
    const int v_row = (lane & 7) + ((lane >> 3) & 1) * 8;
    const int v_col = (lane >> 4) * 16;

    for (int kc = 0; kc < 4; kc++) {
        if (kc < 3) CP_WAIT1(); else CP_WAIT0();
        __syncthreads();
        const unsigned kb = KS + (kc & 1) * 16384;
        const unsigned vb = VS + (kc & 1) * 16384;

        float sacc[16][4];
#pragma unroll
        for (int j = 0; j < 16; j++)
#pragma unroll
            for (int k = 0; k < 4; k++) sacc[j][k] = 0.f;
#pragma unroll
        for (int ks = 0; ks < 4; ks++) {
            unsigned aq[4];
            LDSM4(aq, QS + SWZ((w * 16 + a_row) * 128 + ks * 32 + a_half * 16));
#pragma unroll
            for (int ntp = 0; ntp < 8; ntp++) {
                unsigned bk[4];
                LDSM4(bk, kb + SWZ((ntp * 16 + b_noff) * 128 + ks * 32 + b_half * 16));
                MMA16816(sacc[2 * ntp],     aq, bk[0], bk[1]);
                MMA16816(sacc[2 * ntp + 1], aq, bk[2], bk[3]);
            }
        }
        // ---- online softmax (scale pre-folded into q) ----
        float mx0 = -1e30f, mx1 = -1e30f;
#pragma unroll
        for (int j = 0; j < 16; j++) {
            mx0 = fmaxf(mx0, fmaxf(sacc[j][0], sacc[j][1]));
            mx1 = fmaxf(mx1, fmaxf(sacc[j][2], sacc[j][3]));
        }
        mx0 = fmaxf(mx0, __shfl_xor_sync(0xffffffffu, mx0, 1));
        mx0 = fmaxf(mx0, __shfl_xor_sync(0xffffffffu, mx0, 2));
        mx1 = fmaxf(mx1, __shfl_xor_sync(0xffffffffu, mx1, 1));
        mx1 = fmaxf(mx1, __shfl_xor_sync(0xffffffffu, mx1, 2));
        float nm0 = fmaxf(m0, mx0), nm1 = fmaxf(m1, mx1);
        float al0 = expf(m0 - nm0), al1 = expf(m1 - nm1);
        m0 = nm0; m1 = nm1;
        float rs0 = 0.f, rs1 = 0.f;
#pragma unroll
        for (int j = 0; j < 16; j++) {
            sacc[j][0] = expf(sacc[j][0] - m0); sacc[j][1] = expf(sacc[j][1] - m0);
            sacc[j][2] = expf(sacc[j][2] - m1); sacc[j][3] = expf(sacc[j][3] - m1);
            rs0 += sacc[j][0] + sacc[j][1];
            rs1 += sacc[j][2] + sacc[j][3];
        }
        rs0 += __shfl_xor_sync(0xffffffffu, rs0, 1);
        rs0 += __shfl_xor_sync(0xffffffffu, rs0, 2);
        rs1 += __shfl_xor_sync(0xffffffffu, rs1, 1);
        rs1 += __shfl_xor_sync(0xffffffffu, rs1, 2);
        l0 = l0 * al0 + rs0;
        l1 = l1 * al1 + rs1;
#pragma unroll
        for (int j = 0; j < 8; j++) {
            oacc[j][0] *= al0; oacc[j][1] *= al0;
            oacc[j][2] *= al1; oacc[j][3] *= al1;
        }
#pragma unroll
        for (int ksl = 0; ksl < 8; ksl++) {
            unsigned pa[4];
            pa[0] = pack_bf16x2(sacc[2 * ksl][0],     sacc[2 * ksl][1]);
            pa[1] = pack_bf16x2(sacc[2 * ksl][2],     sacc[2 * ksl][3]);
            pa[2] = pack_bf16x2(sacc[2 * ksl + 1][0], sacc[2 * ksl + 1][1]);
            pa[3] = pack_bf16x2(sacc[2 * ksl + 1][2], sacc[2 * ksl + 1][3]);
#pragma unroll
            for (int ntp = 0; ntp < 4; ntp++) {
                unsigned bv[4];
                LDSM4T(bv, vb + SWZ((ksl * 16 + v_row) * 128 + ntp * 32 + v_col));
                MMA16816(oacc[2 * ntp],     pa, bv[0], bv[1]);
                MMA16816(oacc[2 * ntp + 1], pa, bv[2], bv[3]);
            }
        }
        __syncthreads();
        if (kc + 2 < 4) { loadKV(kc + 2, kc & 1); CP_COMMIT(); }
    }

    float inv0 = 1.f / l0, inv1 = 1.f / l1;
    int row0 = q0 + w * 16 + g;
    __nv_bfloat16* Ob = g_ob + (size_t)(b * SS) * DD + h * DH;
#pragma unroll
    for (int j = 0; j < 8; j++) {
        int col = j * 8 + t4 * 2;
        *(__nv_bfloat162*)(Ob + (size_t)row0 * DD + col) =
            __float22bfloat162_rn(make_float2(oacc[j][0] * inv0, oacc[j][1] * inv0));
        *(__nv_bfloat162*)(Ob + (size_t)(row0 + 8) * DD + col) =
            __float22bfloat162_rn(make_float2(oacc[j][2] * inv1, oacc[j][3] * inv1));
    }
}

// ======================================================================
// weight transpose+pack: src fp32 [K,N] -> dst bf16 [Npad,K] (64x64 tiles)
// ======================================================================
__global__ void __launch_bounds__(256)
packT_k(const float* __restrict__ src, __nv_bfloat16* __restrict__ dst,
        int K, int N, int Npad)
{
    __shared__ float ts[64][65];
    int n0 = blockIdx.x * 64, k0 = blockIdx.y * 64;
    int t = threadIdx.x;
    int kr = t >> 2, cq = t & 3;
#pragma unroll
    for (int i = 0; i < 4; i++) {
        int nc = (cq + i * 4) * 4;
        int n = n0 + nc;
        const float* sp = src + (size_t)(k0 + kr) * N;
        float4 v;
        if (n + 3 < N) v = *(const float4*)(sp + n);
        else {
            v.x = (n + 0 < N) ? sp[n + 0] : 0.f;
            v.y = (n + 1 < N) ? sp[n + 1] : 0.f;
            v.z = (n + 2 < N) ? sp[n + 2] : 0.f;
            v.w = (n + 3 < N) ? sp[n + 3] : 0.f;
        }
        ts[kr][nc] = v.x; ts[kr][nc + 1] = v.y; ts[kr][nc + 2] = v.z; ts[kr][nc + 3] = v.w;
    }
    __syncthreads();
    int nr = t >> 2, ks = (t & 3) * 16;
    if (n0 + nr < Npad) {
        unsigned ov[8];
#pragma unroll
        for (int e = 0; e < 8; e++)
            ov[e] = pack_bf16x2(ts[ks + 2 * e][nr], ts[ks + 2 * e + 1][nr]);
        __nv_bfloat16* dp = dst + (size_t)(n0 + nr) * K + k0 + ks;
        *(uint4*)dp       = make_uint4(ov[0], ov[1], ov[2], ov[3]);
        *(uint4*)(dp + 8) = make_uint4(ov[4], ov[5], ov[6], ov[7]);
    }
}

__global__ void packb_k(const float* __restrict__ bq, const float* __restrict__ bk,
                        const float* __restrict__ bv, float* __restrict__ dst)
{
    int i = blockIdx.x * 256 + threadIdx.x;
    if (i < DD) dst[i] = bq[i];
    else if (i < 2 * DD) dst[i] = bk[i - DD];
    else if (i < 3 * DD) dst[i] = bv[i - 2 * DD];
}

// ======================================================================
// one-hot -> token id (float4 scan, full MLP, no barriers)
// ======================================================================
__global__ void findtok_k(const float* __restrict__ oh, int* __restrict__ tok)
{
    size_t row = blockIdx.x;
    const float4* r = (const float4*)(oh + row * (size_t)VV);
    for (int j = threadIdx.x; j < VV / 4; j += blockDim.x) {
        float4 v = r[j];
        if (v.x > 0.5f) tok[row] = 4 * j;
        else if (v.y > 0.5f) tok[row] = 4 * j + 1;
        else if (v.z > 0.5f) tok[row] = 4 * j + 2;
        else if (v.w > 0.5f) tok[row] = 4 * j + 3;
    }
}

// ======================================================================
// x = se_w[tok] + se_b + positional encoding ; also bf16 mirror
// ======================================================================
__global__ void embed_k(const float* __restrict__ se_w, const float* __restrict__ se_b,
                        const int* __restrict__ tok, float* __restrict__ x,
                        __nv_bfloat16* __restrict__ xb)
{
    int row = blockIdx.x;
    int s   = row & (SS - 1);
    int tk  = tok[row];
    const float* wrow = se_w + (size_t)tk * DD;
    float* xr = x + (size_t)row * DD;
    __nv_bfloat16* xbr = xb + (size_t)row * DD;
    for (int d = threadIdx.x; d < DD; d += blockDim.x) {
        float pe = 0.f;
        if (s != 0) {
            float denom = powf(10000.0f, (2.0f * (float)d) / (float)DD);
            float raw   = (float)s / denom;
            pe = (d & 1) ? cosf(raw) : sinf(raw);
        }
        float v = wrow[d] + se_b[d] + pe;
        xr[d] = v;
        xbr[d] = __float2bfloat16(v);
    }
}

// ======================================================================
// layernorm over D=768 (fp32 in -> bf16 out)
// ======================================================================
__global__ void layernorm_k(const float* __restrict__ y, __nv_bfloat16* __restrict__ x)
{
    __shared__ float rs[8], rq[8];
    size_t row = blockIdx.x;
    const float* yp = y + row * DD;
    __nv_bfloat16* xp = x + row * DD;
    int t = threadIdx.x;
    float a0 = yp[t], a1 = yp[t + 256], a2 = yp[t + 512];
    float s = a0 + a1 + a2;
    float q = a0 * a0 + a1 * a1 + a2 * a2;
#pragma unroll
    for (int o = 16; o; o >>= 1) {
        s += __shfl_xor_sync(0xffffffffu, s, o);
        q += __shfl_xor_sync(0xffffffffu, q, o);
    }
    if ((t & 31) == 0) { rs[t >> 5] = s; rq[t >> 5] = q; }
    __syncthreads();
    s = rs[0] + rs[1] + rs[2] + rs[3] + rs[4] + rs[5] + rs[6] + rs[7];
    q = rq[0] + rq[1] + rq[2] + rq[3] + rq[4] + rq[5] + rq[6] + rq[7];
    float mean = s * (1.0f / (float)DD);
    float var  = q * (1.0f / (float)DD) - mean * mean;
    float r = rsqrtf(var + 1e-5f);
    xp[t]       = __float2bfloat16((a0 - mean) * r);
    xp[t + 256] = __float2bfloat16((a1 - mean) * r);
    xp[t + 512] = __float2bfloat16((a2 - mean) * r);
}

// ======================================================================
// gather masked rows (bf16 -> bf16)
// ======================================================================
__global__ void gather_k(const __nv_bfloat16* __restrict__ x, const int* __restrict__ idx,
                         __nv_bfloat16* __restrict__ g)
{
    int r = blockIdx.x;
    int b = r >> 6;
    int s = idx[r];
    const __nv_bfloat16* src = x + ((size_t)(b * SS + s)) * DD;
    __nv_bfloat16* dst = g + (size_t)r * DD;
    for (int d = threadIdx.x; d < DD; d += blockDim.x) dst[d] = src[d];
}

// ======================================================================
// in-place log_softmax over V=30000 — single gmem read via smem staging
// ======================================================================
__global__ void logsoftmax_k(float* __restrict__ out)
{
    extern __shared__ float buf[];       // 30000 floats = 117.2 KB
    __shared__ float red[8];
    size_t row = blockIdx.x;
    float* p = out + row * (size_t)VV;
    int t = threadIdx.x;

    float m = -1e30f;
    for (int j = t; j < VV / 4; j += 256) {
        float4 v = *(const float4*)(p + 4 * j);
        *(float4*)(buf + 4 * j) = v;
        m = fmaxf(fmaxf(m, fmaxf(v.x, v.y)), fmaxf(v.z, v.w));
    }
#pragma unroll
    for (int o = 16; o; o >>= 1) m = fmaxf(m, __shfl_xor_sync(0xffffffffu, m, o));
    if ((t & 31) == 0) red[t >> 5] = m;
    __syncthreads();
    m = fmaxf(fmaxf(fmaxf(red[0], red[1]), fmaxf(red[2], red[3])),
              fmaxf(fmaxf(red[4], red[5]), fmaxf(red[6], red[7])));

    float s = 0.f;
    for (int j = t; j < VV / 4; j += 256) {
        float4 v = *(const float4*)(buf + 4 * j);
        s += expf(v.x - m) + expf(v.y - m) + expf(v.z - m) + expf(v.w - m);
    }
#pragma unroll
    for (int o = 16; o; o >>= 1) s += __shfl_xor_sync(0xffffffffu, s, o);
    __syncthreads();
    if ((t & 31) == 0) red[t >> 5] = s;
    __syncthreads();
    s = red[0] + red[1] + red[2] + red[3] + red[4] + red[5] + red[6] + red[7];

    float lse = m + logf(s);
    for (int j = t; j < VV / 4; j += 256) {
        float4 v = *(const float4*)(buf + 4 * j);
        *(float4*)(p + 4 * j) = make_float4(v.x - lse, v.y - lse, v.z - lse, v.w - lse);
    }
}

// ======================================================================
// launcher
// ======================================================================
extern "C" void kernel_launch(void* const* d_in, const int* in_sizes, int n_in,
                              void* d_out, int out_size)
{
    (void)in_sizes; (void)n_in; (void)out_size;
    const float* onehot = (const float*)d_in[0];
    const float* se_w = (const float*)d_in[1];
    const float* se_b = (const float*)d_in[2];
    const float* wq = (const float*)d_in[3];  const float* bq = (const float*)d_in[4];
    const float* wk = (const float*)d_in[5];  const float* bk = (const float*)d_in[6];
    const float* wv = (const float*)d_in[7];  const float* bv = (const float*)d_in[8];
    const float* wo = (const float*)d_in[9];  const float* bo = (const float*)d_in[10];
    const float* w1 = (const float*)d_in[11]; const float* b1 = (const float*)d_in[12];
    const float* w2 = (const float*)d_in[13]; const float* b2 = (const float*)d_in[14];
    const float* we = (const float*)d_in[15]; const float* be = (const float*)d_in[16];
    const int*   idx = (const int*)d_in[17];
    float* out = (float*)d_out;

    float *px, *py, *pbqkv;
    __nv_bfloat16 *pxb, *plnb, *pob, *ph1b, *pgb;
    __nv_bfloat16 *pwqkv, *pwow, *pw1w, *pw2w, *pwew;
    int* ptok;
    cudaGetSymbolAddress((void**)&px,    g_x);
    cudaGetSymbolAddress((void**)&py,    g_y);
    cudaGetSymbolAddress((void**)&pbqkv, g_bqkv);
    cudaGetSymbolAddress((void**)&pxb,   g_xb);
    cudaGetSymbolAddress((void**)&plnb,  g_lnb);
    cudaGetSymbolAddress((void**)&pob,   g_ob);
    cudaGetSymbolAddress((void**)&ph1b,  g_h1b);
    cudaGetSymbolAddress((void**)&pgb,   g_gb);
    cudaGetSymbolAddress((void**)&pwqkv, g_wqkv);
    cudaGetSymbolAddress((void**)&pwow,  g_wow);
    cudaGetSymbolAddress((void**)&pw1w,  g_w1w);
    cudaGetSymbolAddress((void**)&pw2w,  g_w2w);
    cudaGetSymbolAddress((void**)&pwew,  g_wew);
    cudaGetSymbolAddress((void**)&ptok,  g_tok);

    const int SMG128 = 3 * (16384 + 16384);   // 98304
    const int SMG64  = 3 * (8192 + 16384);    // 73728
    const int SMA = 16384 + 32768 + 32768;    // 81920
    const int SML = VV * 4;                   // 120000
    cudaFuncSetAttribute((const void*)tgemm_k<EP_QKV,  128, 2>,
                         cudaFuncAttributeMaxDynamicSharedMemorySize, SMG128);
    cudaFuncSetAttribute((const void*)tgemm_k<EP_OPROJ, 64, 3>,
                         cudaFuncAttributeMaxDynamicSharedMemorySize, SMG64);
    cudaFuncSetAttribute((const void*)tgemm_k<EP_FFN1, 128, 2>,
                         cudaFuncAttributeMaxDynamicSharedMemorySize, SMG128);
    cudaFuncSetAttribute((const void*)tgemm_k<EP_FFN2,  64, 3>,
                         cudaFuncAttributeMaxDynamicSharedMemorySize, SMG64);
    cudaFuncSetAttribute((const void*)tgemm_k<EP_HEAD, 128, 2>,
                         cudaFuncAttributeMaxDynamicSharedMemorySize, SMG128);
    cudaFuncSetAttribute((const void*)fattn_k,
                         cudaFuncAttributeMaxDynamicSharedMemorySize, SMA);
    cudaFuncSetAttribute((const void*)logsoftmax_k,
                         cudaFuncAttributeMaxDynamicSharedMemorySize, SML);

    // ---- stream fork: weight packs overlap the one-hot scan/embedding ----
    static cudaStream_t sPack = nullptr;
    static cudaEvent_t  evFork = nullptr, evJoin = nullptr;
    if (sPack == nullptr) {
        if (cudaStreamCreateWithFlags(&sPack, cudaStreamNonBlocking) != cudaSuccess)
            sPack = nullptr;
        if (sPack) {
            cudaEventCreateWithFlags(&evFork, cudaEventDisableTiming);
            cudaEventCreateWithFlags(&evJoin, cudaEventDisableTiming);
        }
    }
    cudaStream_t sp = sPack ? sPack : (cudaStream_t)0;
    if (sPack) {
        cudaEventRecord(evFork, 0);
        cudaStreamWaitEvent(sPack, evFork, 0);
    }

    // ---- weight/bias packing (bf16, [N,K]) on side stream ----
    packb_k<<<9, 256, 0, sp>>>(bq, bk, bv, pbqkv);
    packT_k<<<dim3(12, 12), 256, 0, sp>>>(wq, pwqkv,               DD, DD, DD);
    packT_k<<<dim3(12, 12), 256, 0, sp>>>(wk, pwqkv + DD * DD,     DD, DD, DD);
    packT_k<<<dim3(12, 12), 256, 0, sp>>>(wv, pwqkv + 2 * DD * DD, DD, DD, DD);
    packT_k<<<dim3(12, 12), 256, 0, sp>>>(wo, pwow,                DD, DD, DD);
    packT_k<<<dim3(48, 12), 256, 0, sp>>>(w1, pw1w,                DD, FF_, FF_);
    packT_k<<<dim3(12, 48), 256, 0, sp>>>(w2, pw2w,                FF_, DD, DD);
    packT_k<<<dim3(470, 12), 256, 0, sp>>>(we, pwew,               DD, VV, VPAD);
    if (sPack) cudaEventRecord(evJoin, sPack);

    // ---- embedding on default stream (concurrent with packs) ----
    findtok_k<<<BB * SS, 256>>>(onehot, ptok);
    embed_k<<<BB * SS, 256>>>(se_w, se_b, ptok, px, pxb);

    if (sPack) cudaStreamWaitEvent((cudaStream_t)0, evJoin, 0);

    for (int l = 0; l < NLAYERS; l++) {
        // QKV fused: [2048,768] @ [2304,768]^T -> per-head q/k/v (bf16)
        tgemm_k<EP_QKV, 128, 2><<<dim3(18, 16), 256, SMG128>>>(
            pxb, pwqkv, DD, DD, DD, pbqkv, nullptr);

        // fused attention -> g_ob (bf16, heads concatenated)
        fattn_k<<<dim3(SS / 128, BB * HH), 256, SMA>>>();

        // o @ wo + bo + x -> y (fp32)   [64x128 tiles -> 192 CTAs, occ 3]
        tgemm_k<EP_OPROJ, 64, 3><<<dim3(6, 32), 256, SMG64>>>(
            pob, pwow, DD, DD, DD, bo, nullptr);

        layernorm_k<<<BB * SS, 256>>>(py, plnb);

        // relu(ln @ w1 + b1) -> h1b (bf16)   [128x128 tiles -> 384 CTAs]
        tgemm_k<EP_FFN1, 128, 2><<<dim3(24, 16), 256, SMG128>>>(
            plnb, pw1w, DD, DD, DD, b1, nullptr);

        // h1 @ w2 + b2 -> x (fp32) + xb (bf16)   [64x128 tiles -> 192 CTAs, occ 3]
        tgemm_k<EP_FFN2, 64, 3><<<dim3(6, 32), 256, SMG64>>>(
            ph1b, pw2w, FF_, FF_, FF_, b2, nullptr);
    }

    // gather + vocab head + log_softmax
    gather_k<<<BB * MM, 256>>>(pxb, idx, pgb);
    tgemm_k<EP_HEAD, 128, 2><<<dim3(VPAD / 128, 2), 256, SMG128>>>(
        pgb, pwew, DD, DD, DD, be, out);
    logsoftmax_k<<<BB * MM, 256, SML>>>(out);
}